// round 10
// baseline (speedup 1.0000x reference)
#include <cuda_runtime.h>

typedef unsigned long long u64;

#define BB 384          // N*L = 32*12
#define CV 12800        // C*V = 32*400
#define VSQ 160000      // V*V
#define AL 0.05f
#define OMA 0.95f

// ---------------- static device scratch ----------------
__device__ float g_xr [BB*CV];     // x repacked planar [b][c][v]
__device__ float g_x1 [BB*CV];
__device__ float g_x2 [BB*CV];
__device__ float g_E  [BB*VSQ];    // exp(adj)  [b][v][w]
__device__ float g_ET [BB*VSQ];    // transpose [b][w][v]
__device__ float g_rs [BB*400];    // row sums of E
__device__ float g_cs [BB*400];    // col sums of E
__device__ float g_csp[7*BB*400];  // colsum partials (deterministic)
__device__ float g_h10[BB*CV];
__device__ float g_h20[BB*CV];
__device__ float g_h11[BB*CV];
__device__ float g_h21[BB*CV];

// ---------------- f32x2 helpers ----------------
__device__ __forceinline__ u64 ffma2(u64 a, u64 b, u64 c) {
    u64 d; asm("fma.rn.f32x2 %0,%1,%2,%3;" : "=l"(d) : "l"(a), "l"(b), "l"(c)); return d;
}
__device__ __forceinline__ u64 pack2(float x, float y) {
    u64 r; asm("mov.b64 %0,{%1,%2};" : "=l"(r) : "f"(x), "f"(y)); return r;
}
__device__ __forceinline__ u64 dup2(float x) { return pack2(x, x); }
__device__ __forceinline__ float2 unp2(u64 v) {
    float2 f; asm("mov.b64 {%0,%1},%2;" : "=f"(f.x), "=f"(f.y) : "l"(v)); return f;
}

// ================= K1: lin1/lin2 + tanh + planar repack =================
__global__ void __launch_bounds__(256) k1(const float* __restrict__ x,
    const float* __restrict__ w1, const float* __restrict__ b1,
    const float* __restrict__ w2, const float* __restrict__ b2)
{
    __shared__ u64 w1p[32][16], w2p[32][16];
    __shared__ u64 b1p[16], b2p[16];
    int t = threadIdx.x, b = blockIdx.x;
    int n = b / 12, l = b - n * 12;
    for (int i = t; i < 512; i += 256) {
        int ci = i >> 4, k = i & 15;
        w1p[ci][k] = pack2(w1[(2*k)*32 + ci], w1[(2*k+1)*32 + ci]);
        w2p[ci][k] = pack2(w2[(2*k)*32 + ci], w2[(2*k+1)*32 + ci]);
    }
    if (t < 16) {
        b1p[t] = pack2(b1[2*t], b1[2*t+1]);
        b2p[t] = pack2(b2[2*t], b2[2*t+1]);
    }
    __syncthreads();
    for (int v = t; v < 400; v += 256) {
        float xv[32];
        #pragma unroll
        for (int c = 0; c < 32; c++) xv[c] = x[((n*32 + c)*400 + v)*12 + l];
        #pragma unroll
        for (int c = 0; c < 32; c++) g_xr[b*CV + c*400 + v] = xv[c];

        u64 acc[16];
        #pragma unroll
        for (int k = 0; k < 16; k++) acc[k] = b1p[k];
        #pragma unroll
        for (int c = 0; c < 32; c++) {
            u64 d = dup2(xv[c]);
            #pragma unroll
            for (int k = 0; k < 16; k++) acc[k] = ffma2(w1p[c][k], d, acc[k]);
        }
        #pragma unroll
        for (int k = 0; k < 16; k++) {
            float2 r = unp2(acc[k]);
            g_x1[b*CV + (2*k)*400   + v] = tanhf(r.x);
            g_x1[b*CV + (2*k+1)*400 + v] = tanhf(r.y);
        }
        #pragma unroll
        for (int k = 0; k < 16; k++) acc[k] = b2p[k];
        #pragma unroll
        for (int c = 0; c < 32; c++) {
            u64 d = dup2(xv[c]);
            #pragma unroll
            for (int k = 0; k < 16; k++) acc[k] = ffma2(w2p[c][k], d, acc[k]);
        }
        #pragma unroll
        for (int k = 0; k < 16; k++) {
            float2 r = unp2(acc[k]);
            g_x2[b*CV + (2*k)*400   + v] = tanhf(r.x);
            g_x2[b*CV + (2*k+1)*400 + v] = tanhf(r.y);
        }
    }
}

// ================= K2: adjacency + exp + E/ET + row sums + colsum partials =================
// block: 416 threads (13 warps), covers w=0..399 for 2*NP v-rows starting at v0.
template<int NP>
__global__ void __launch_bounds__(416) k2(int v0base, int tilebase)
{
    __shared__ u64 x1p[32][NP];
    __shared__ float wred[2*NP][13];
    int t = threadIdx.x, b = blockIdx.x;
    int v0 = v0base + blockIdx.y * 64;
    int tile = tilebase + blockIdx.y;

    for (int i = t; i < 32*NP; i += 416) {
        int c = i / NP, k = i - c*NP;
        const float2* s = (const float2*)(g_x1 + b*CV + c*400 + v0);
        float2 p = s[k];
        x1p[c][k] = pack2(p.x, p.y);
    }
    __syncthreads();

    bool act = t < 400;
    int w = t;
    u64 acc[NP];
    #pragma unroll
    for (int k = 0; k < NP; k++) acc[k] = 0ULL;
    if (act) {
        const float* x2b = g_x2 + b*CV + w;
        #pragma unroll
        for (int c = 0; c < 32; c++) {
            u64 d = dup2(x2b[c*400]);
            #pragma unroll
            for (int k = 0; k < NP; k++) acc[k] = ffma2(x1p[c][k], d, acc[k]);
        }
    }

    float cw = 0.f;
    float* Eb  = g_E  + b*VSQ;
    float* ETb = g_ET + b*VSQ;
    int lane = t & 31, wp = t >> 5;
    #pragma unroll
    for (int q = 0; q < NP/2; q++) {
        float e0 = 0.f, e1 = 0.f, e2 = 0.f, e3 = 0.f;
        int v = v0 + 4*q;
        if (act) {
            float2 r0 = unp2(acc[2*q]), r1 = unp2(acc[2*q + 1]);
            e0 = __expf(r0.x); e1 = __expf(r0.y); e2 = __expf(r1.x); e3 = __expf(r1.y);
            Eb[(v+0)*400 + w] = e0;
            Eb[(v+1)*400 + w] = e1;
            Eb[(v+2)*400 + w] = e2;
            Eb[(v+3)*400 + w] = e3;
            *(float4*)(ETb + w*400 + v) = make_float4(e0, e1, e2, e3);
            cw += e0 + e1 + e2 + e3;
        }
        float s0 = e0, s1 = e1, s2 = e2, s3 = e3;
        #pragma unroll
        for (int off = 16; off; off >>= 1) {
            s0 += __shfl_xor_sync(0xffffffffu, s0, off);
            s1 += __shfl_xor_sync(0xffffffffu, s1, off);
            s2 += __shfl_xor_sync(0xffffffffu, s2, off);
            s3 += __shfl_xor_sync(0xffffffffu, s3, off);
        }
        if (lane == 0) {
            wred[4*q+0][wp] = s0; wred[4*q+1][wp] = s1;
            wred[4*q+2][wp] = s2; wred[4*q+3][wp] = s3;
        }
    }
    __syncthreads();
    if (t < 2*NP) {
        float s = 0.f;
        #pragma unroll
        for (int j = 0; j < 13; j++) s += wred[t][j];
        g_rs[b*400 + v0 + t] = s;
    }
    if (act) g_csp[tile*(BB*400) + b*400 + w] = cw;
}

// ================= K3: colsum reduce =================
__global__ void __launch_bounds__(256) k3()
{
    int i = blockIdx.x * 256 + threadIdx.x;   // 153600 total
    float s = 0.f;
    #pragma unroll
    for (int j = 0; j < 7; j++) s += g_csp[j*(BB*400) + i];
    g_cs[i] = s;
}

// ================= K4: fused 2-step diffusion (one block per (b,chain)) =================
__global__ void __launch_bounds__(256) k4()
{
    extern __shared__ float sm[];
    float* As   = sm;              // [400][34] padded pairs: As[v][c] = h[c][v]/s[v]
    float* sinv = sm + 400*34;     // [400]
    int t = threadIdx.x, b = blockIdx.x, ch = blockIdx.y;
    const float* E  = (ch ? g_ET  : g_E ) + b*VSQ;
    const float* sv = (ch ? g_cs  : g_rs) + b*400;
    float* h1 = (ch ? g_h11 : g_h10) + b*CV;
    float* h2 = (ch ? g_h21 : g_h20) + b*CV;
    const float* xr = g_xr + b*CV;

    for (int v = t; v < 400; v += 256) sinv[v] = 1.0f / sv[v];
    __syncthreads();
    for (int i = t; i < CV; i += 256) {
        int c = i / 400, v = i - c*400;
        As[v*34 + c] = xr[i] * sinv[v];
    }
    __syncthreads();

    int w1 = t;
    int w2 = t + 256;
    bool ok2 = w2 < 400;

    for (int step = 0; step < 2; step++) {
        u64 a1[16], a2[16];
        #pragma unroll
        for (int k = 0; k < 16; k++) { a1[k] = 0ULL; a2[k] = 0ULL; }

        if ((t >> 5) < 5) {
            // warps 0..4: dual w-column path
            float ea0 = E[w1], ea1 = E[400 + w1];
            float eb0 = ok2 ? E[w2] : 0.f;
            float eb1 = ok2 ? E[400 + w2] : 0.f;
            for (int v = 0; v < 400; v += 2) {
                float ca0 = ea0, ca1 = ea1, cb0 = eb0, cb1 = eb1;
                if (v + 2 < 400) {
                    ea0 = E[(v+2)*400 + w1]; ea1 = E[(v+3)*400 + w1];
                    if (ok2) { eb0 = E[(v+2)*400 + w2]; eb1 = E[(v+3)*400 + w2]; }
                }
                u64 da = dup2(ca0), db = dup2(cb0);
                const u64* Ar = (const u64*)(As + v*34);
                #pragma unroll
                for (int k = 0; k < 16; k++) {
                    u64 a = Ar[k];
                    a1[k] = ffma2(a, da, a1[k]);
                    a2[k] = ffma2(a, db, a2[k]);
                }
                da = dup2(ca1); db = dup2(cb1);
                const u64* Ar2 = (const u64*)(As + (v+1)*34);
                #pragma unroll
                for (int k = 0; k < 16; k++) {
                    u64 a = Ar2[k];
                    a1[k] = ffma2(a, da, a1[k]);
                    a2[k] = ffma2(a, db, a2[k]);
                }
            }
        } else {
            // warps 5..7: single w-column path
            float ea0 = E[w1], ea1 = E[400 + w1];
            for (int v = 0; v < 400; v += 2) {
                float ca0 = ea0, ca1 = ea1;
                if (v + 2 < 400) { ea0 = E[(v+2)*400 + w1]; ea1 = E[(v+3)*400 + w1]; }
                u64 da = dup2(ca0);
                const u64* Ar = (const u64*)(As + v*34);
                #pragma unroll
                for (int k = 0; k < 16; k++) a1[k] = ffma2(Ar[k], da, a1[k]);
                da = dup2(ca1);
                const u64* Ar2 = (const u64*)(As + (v+1)*34);
                #pragma unroll
                for (int k = 0; k < 16; k++) a1[k] = ffma2(Ar2[k], da, a1[k]);
            }
        }

        __syncthreads();   // all reads of As done before overwrite
        float* hout = step ? h2 : h1;
        {
            float si = sinv[w1];
            #pragma unroll
            for (int k = 0; k < 16; k++) {
                float2 r = unp2(a1[k]);
                float x0 = xr[(2*k)*400 + w1], x1v = xr[(2*k+1)*400 + w1];
                float o0 = AL*x0 + OMA*r.x, o1 = AL*x1v + OMA*r.y;
                hout[(2*k)*400 + w1] = o0;
                hout[(2*k+1)*400 + w1] = o1;
                if (step == 0) { As[w1*34 + 2*k] = o0*si; As[w1*34 + 2*k + 1] = o1*si; }
            }
        }
        if (ok2) {
            float si = sinv[w2];
            #pragma unroll
            for (int k = 0; k < 16; k++) {
                float2 r = unp2(a2[k]);
                float x0 = xr[(2*k)*400 + w2], x1v = xr[(2*k+1)*400 + w2];
                float o0 = AL*x0 + OMA*r.x, o1 = AL*x1v + OMA*r.y;
                hout[(2*k)*400 + w2] = o0;
                hout[(2*k+1)*400 + w2] = o1;
                if (step == 0) { As[w2*34 + 2*k] = o0*si; As[w2*34 + 2*k + 1] = o1*si; }
            }
        }
        __syncthreads();   // As ready for next step
    }
}

// ================= K5: combined MLP (160-wide) + output =================
__global__ void __launch_bounds__(256) k5(const float* __restrict__ wm1, const float* __restrict__ bm1,
                                          const float* __restrict__ wm2, const float* __restrict__ bm2,
                                          float* __restrict__ out)
{
    __shared__ u64 wc[160][16];
    __shared__ u64 bc[16];
    __shared__ const float* catp[160];
    int t = threadIdx.x, b = blockIdx.x;

    for (int i = t; i < 2560; i += 256) {
        int j = i >> 4, k = i & 15;
        float v0, v1;
        if (j < 32) {
            v0 = wm1[(2*k)*96 + j]   + wm2[(2*k)*96 + j];
            v1 = wm1[(2*k+1)*96 + j] + wm2[(2*k+1)*96 + j];
        } else if (j < 96) {
            v0 = wm1[(2*k)*96 + j];
            v1 = wm1[(2*k+1)*96 + j];
        } else {
            v0 = wm2[(2*k)*96 + j - 64];
            v1 = wm2[(2*k+1)*96 + j - 64];
        }
        wc[j][k] = pack2(v0, v1);
    }
    if (t < 16) bc[t] = pack2(bm1[2*t] + bm2[2*t], bm1[2*t+1] + bm2[2*t+1]);
    if (t < 160) {
        const float* p;
        if (t < 32)       p = g_xr  + b*CV + t*400;
        else if (t < 64)  p = g_h10 + b*CV + (t-32)*400;
        else if (t < 96)  p = g_h20 + b*CV + (t-64)*400;
        else if (t < 128) p = g_h11 + b*CV + (t-96)*400;
        else              p = g_h21 + b*CV + (t-128)*400;
        catp[t] = p;
    }
    __syncthreads();

    int n = b / 12, l = b - n*12;
    for (int w = t; w < 400; w += 256) {
        u64 acc[16];
        #pragma unroll
        for (int k = 0; k < 16; k++) acc[k] = bc[k];
        #pragma unroll 4
        for (int j = 0; j < 160; j++) {
            u64 d = dup2(catp[j][w]);
            #pragma unroll
            for (int k = 0; k < 16; k++) acc[k] = ffma2(wc[j][k], d, acc[k]);
        }
        #pragma unroll
        for (int k = 0; k < 16; k++) {
            float2 r = unp2(acc[k]);
            out[((n*32 + 2*k)*400 + w)*12 + l]   = r.x;
            out[((n*32 + 2*k+1)*400 + w)*12 + l] = r.y;
        }
    }
}

// ================= launch =================
extern "C" void kernel_launch(void* const* d_in, const int* in_sizes, int n_in,
                              void* d_out, int out_size)
{
    const float* x   = (const float*)d_in[0];
    const float* w1  = (const float*)d_in[1];
    const float* b1  = (const float*)d_in[2];
    const float* w2  = (const float*)d_in[3];
    const float* b2  = (const float*)d_in[4];
    const float* wm1 = (const float*)d_in[5];
    const float* bm1 = (const float*)d_in[6];
    const float* wm2 = (const float*)d_in[7];
    const float* bm2 = (const float*)d_in[8];
    float* out = (float*)d_out;

    cudaFuncSetAttribute(k4, cudaFuncAttributeMaxDynamicSharedMemorySize, (400*34 + 400) * 4);

    k1<<<384, 256>>>(x, w1, b1, w2, b2);
    k2<32><<<dim3(384, 6), 416>>>(0, 0);     // v-tiles 0..5 (64 rows each)
    k2<8><<<dim3(384, 1), 416>>>(384, 6);    // tail tile (16 rows)
    k3<<<600, 256>>>();
    k4<<<dim3(384, 2), 256, (400*34 + 400) * 4>>>();
    k5<<<384, 256>>>(wm1, bm1, wm2, bm2, out);
}

// round 11
// speedup vs baseline: 1.0902x; 1.0902x over previous
#include <cuda_runtime.h>

typedef unsigned long long u64;

#define BB 384          // N*L = 32*12
#define CV 12800        // C*V = 32*400
#define VSQ 160000      // V*V
#define AL 0.05f
#define OMA 0.95f

// ---------------- static device scratch ----------------
__device__ float g_xr [BB*CV];     // x repacked planar [b][c][v]
__device__ float g_x1 [BB*CV];
__device__ float g_x2 [BB*CV];
__device__ float g_E  [BB*VSQ];    // exp(adj)  [b][v][w]
__device__ float g_ET [BB*VSQ];    // transpose [b][w][v]
__device__ float g_rs [BB*400];    // row sums of E
__device__ float g_cs [BB*400];    // col sums of E
__device__ float g_csp[7*BB*400];  // colsum partials (deterministic)
__device__ float g_h10[BB*CV];
__device__ float g_h20[BB*CV];
__device__ float g_h11[BB*CV];
__device__ float g_h21[BB*CV];

// ---------------- f32x2 helpers ----------------
__device__ __forceinline__ u64 ffma2(u64 a, u64 b, u64 c) {
    u64 d; asm("fma.rn.f32x2 %0,%1,%2,%3;" : "=l"(d) : "l"(a), "l"(b), "l"(c)); return d;
}
__device__ __forceinline__ u64 pack2(float x, float y) {
    u64 r; asm("mov.b64 %0,{%1,%2};" : "=l"(r) : "f"(x), "f"(y)); return r;
}
__device__ __forceinline__ u64 dup2(float x) { return pack2(x, x); }
__device__ __forceinline__ float2 unp2(u64 v) {
    float2 f; asm("mov.b64 {%0,%1},%2;" : "=f"(f.x), "=f"(f.y) : "l"(v)); return f;
}

// ================= K1: lin1/lin2 + tanh + planar repack =================
__global__ void __launch_bounds__(256) k1(const float* __restrict__ x,
    const float* __restrict__ w1, const float* __restrict__ b1,
    const float* __restrict__ w2, const float* __restrict__ b2)
{
    __shared__ u64 w1p[32][16], w2p[32][16];
    __shared__ u64 b1p[16], b2p[16];
    int t = threadIdx.x, b = blockIdx.x;
    int n = b / 12, l = b - n * 12;
    for (int i = t; i < 512; i += 256) {
        int ci = i >> 4, k = i & 15;
        w1p[ci][k] = pack2(w1[(2*k)*32 + ci], w1[(2*k+1)*32 + ci]);
        w2p[ci][k] = pack2(w2[(2*k)*32 + ci], w2[(2*k+1)*32 + ci]);
    }
    if (t < 16) {
        b1p[t] = pack2(b1[2*t], b1[2*t+1]);
        b2p[t] = pack2(b2[2*t], b2[2*t+1]);
    }
    __syncthreads();
    for (int v = t; v < 400; v += 256) {
        float xv[32];
        #pragma unroll
        for (int c = 0; c < 32; c++) xv[c] = x[((n*32 + c)*400 + v)*12 + l];
        #pragma unroll
        for (int c = 0; c < 32; c++) g_xr[b*CV + c*400 + v] = xv[c];

        u64 acc[16];
        #pragma unroll
        for (int k = 0; k < 16; k++) acc[k] = b1p[k];
        #pragma unroll
        for (int c = 0; c < 32; c++) {
            u64 d = dup2(xv[c]);
            #pragma unroll
            for (int k = 0; k < 16; k++) acc[k] = ffma2(w1p[c][k], d, acc[k]);
        }
        #pragma unroll
        for (int k = 0; k < 16; k++) {
            float2 r = unp2(acc[k]);
            g_x1[b*CV + (2*k)*400   + v] = tanhf(r.x);
            g_x1[b*CV + (2*k+1)*400 + v] = tanhf(r.y);
        }
        #pragma unroll
        for (int k = 0; k < 16; k++) acc[k] = b2p[k];
        #pragma unroll
        for (int c = 0; c < 32; c++) {
            u64 d = dup2(xv[c]);
            #pragma unroll
            for (int k = 0; k < 16; k++) acc[k] = ffma2(w2p[c][k], d, acc[k]);
        }
        #pragma unroll
        for (int k = 0; k < 16; k++) {
            float2 r = unp2(acc[k]);
            g_x2[b*CV + (2*k)*400   + v] = tanhf(r.x);
            g_x2[b*CV + (2*k+1)*400 + v] = tanhf(r.y);
        }
    }
}

// ================= K2: adjacency + exp + E/ET + row sums + colsum partials =================
// block: 416 threads (13 warps), covers w=0..399 for 2*NP v-rows starting at v0.
template<int NP>
__global__ void __launch_bounds__(416) k2(int v0base, int tilebase)
{
    __shared__ u64 x1p[32][NP];
    __shared__ float wred[2*NP][13];
    int t = threadIdx.x, b = blockIdx.x;
    int v0 = v0base + blockIdx.y * 64;
    int tile = tilebase + blockIdx.y;

    for (int i = t; i < 32*NP; i += 416) {
        int c = i / NP, k = i - c*NP;
        const float2* s = (const float2*)(g_x1 + b*CV + c*400 + v0);
        float2 p = s[k];
        x1p[c][k] = pack2(p.x, p.y);
    }
    __syncthreads();

    bool act = t < 400;
    int w = t;
    u64 acc[NP];
    #pragma unroll
    for (int k = 0; k < NP; k++) acc[k] = 0ULL;
    if (act) {
        const float* x2b = g_x2 + b*CV + w;
        #pragma unroll
        for (int c = 0; c < 32; c++) {
            u64 d = dup2(x2b[c*400]);
            #pragma unroll
            for (int k = 0; k < NP; k++) acc[k] = ffma2(x1p[c][k], d, acc[k]);
        }
    }

    float cw = 0.f;
    float* Eb  = g_E  + b*VSQ;
    float* ETb = g_ET + b*VSQ;
    int lane = t & 31, wp = t >> 5;
    #pragma unroll
    for (int q = 0; q < NP/2; q++) {
        float e0 = 0.f, e1 = 0.f, e2 = 0.f, e3 = 0.f;
        int v = v0 + 4*q;
        if (act) {
            float2 r0 = unp2(acc[2*q]), r1 = unp2(acc[2*q + 1]);
            e0 = __expf(r0.x); e1 = __expf(r0.y); e2 = __expf(r1.x); e3 = __expf(r1.y);
            Eb[(v+0)*400 + w] = e0;
            Eb[(v+1)*400 + w] = e1;
            Eb[(v+2)*400 + w] = e2;
            Eb[(v+3)*400 + w] = e3;
            *(float4*)(ETb + w*400 + v) = make_float4(e0, e1, e2, e3);
            cw += e0 + e1 + e2 + e3;
        }
        float s0 = e0, s1 = e1, s2 = e2, s3 = e3;
        #pragma unroll
        for (int off = 16; off; off >>= 1) {
            s0 += __shfl_xor_sync(0xffffffffu, s0, off);
            s1 += __shfl_xor_sync(0xffffffffu, s1, off);
            s2 += __shfl_xor_sync(0xffffffffu, s2, off);
            s3 += __shfl_xor_sync(0xffffffffu, s3, off);
        }
        if (lane == 0) {
            wred[4*q+0][wp] = s0; wred[4*q+1][wp] = s1;
            wred[4*q+2][wp] = s2; wred[4*q+3][wp] = s3;
        }
    }
    __syncthreads();
    if (t < 2*NP) {
        float s = 0.f;
        #pragma unroll
        for (int j = 0; j < 13; j++) s += wred[t][j];
        g_rs[b*400 + v0 + t] = s;
    }
    if (act) g_csp[tile*(BB*400) + b*400 + w] = cw;
}

// ================= K3: colsum reduce =================
__global__ void __launch_bounds__(256) k3()
{
    int i = blockIdx.x * 256 + threadIdx.x;   // 153600 total
    float s = 0.f;
    #pragma unroll
    for (int j = 0; j < 7; j++) s += g_csp[j*(BB*400) + i];
    g_cs[i] = s;
}

// ================= K4: fused 2-step diffusion, branch-free mainloop =================
__global__ void __launch_bounds__(256) k4()
{
    extern __shared__ float sm[];
    float* As   = sm;              // [400][34] padded pairs: As[v][c] = h[c][v]/s[v]
    float* sinv = sm + 400*34;     // [400]
    int t = threadIdx.x, b = blockIdx.x, ch = blockIdx.y;
    const float* E  = (ch ? g_ET  : g_E ) + b*VSQ;
    const float* sv = (ch ? g_cs  : g_rs) + b*400;
    float* h1 = (ch ? g_h11 : g_h10) + b*CV;
    float* h2 = (ch ? g_h21 : g_h20) + b*CV;
    const float* xr = g_xr + b*CV;

    for (int v = t; v < 400; v += 256) sinv[v] = 1.0f / sv[v];
    __syncthreads();
    for (int i = t; i < CV; i += 256) {
        int c = i / 400, v = i - c*400;
        As[v*34 + c] = xr[i] * sinv[v];
    }
    __syncthreads();

    int w1 = t;
    int w2 = t + 256;
    bool ok2 = w2 < 400;
    int w2c = ok2 ? w2 : 399;      // clamped: compute path always valid

    for (int step = 0; step < 2; step++) {
        u64 a1[16], a2[16];
        #pragma unroll
        for (int k = 0; k < 16; k++) { a1[k] = 0ULL; a2[k] = 0ULL; }

        if ((t >> 5) < 5) {
            // warps 0..4: dual w-column, branch-free, 4-row prefetch
            float ea[4], eb[4];
            #pragma unroll
            for (int j = 0; j < 4; j++) { ea[j] = E[j*400 + w1]; eb[j] = E[j*400 + w2c]; }
            for (int v = 0; v < 400; v += 4) {
                float ca[4], cb[4];
                #pragma unroll
                for (int j = 0; j < 4; j++) { ca[j] = ea[j]; cb[j] = eb[j]; }
                int vp = (v + 4 < 400) ? v + 4 : 0;   // SEL, no branch
                #pragma unroll
                for (int j = 0; j < 4; j++) { ea[j] = E[(vp+j)*400 + w1]; eb[j] = E[(vp+j)*400 + w2c]; }
                #pragma unroll
                for (int j = 0; j < 4; j++) {
                    u64 da = dup2(ca[j]), db = dup2(cb[j]);
                    const u64* Ar = (const u64*)(As + (v+j)*34);
                    #pragma unroll
                    for (int k = 0; k < 16; k++) {
                        u64 a = Ar[k];
                        a1[k] = ffma2(a, da, a1[k]);
                        a2[k] = ffma2(a, db, a2[k]);
                    }
                }
            }
        } else {
            // warps 5..7: single w-column, branch-free, 4-row prefetch
            float ea[4];
            #pragma unroll
            for (int j = 0; j < 4; j++) ea[j] = E[j*400 + w1];
            for (int v = 0; v < 400; v += 4) {
                float ca[4];
                #pragma unroll
                for (int j = 0; j < 4; j++) ca[j] = ea[j];
                int vp = (v + 4 < 400) ? v + 4 : 0;
                #pragma unroll
                for (int j = 0; j < 4; j++) ea[j] = E[(vp+j)*400 + w1];
                #pragma unroll
                for (int j = 0; j < 4; j++) {
                    u64 da = dup2(ca[j]);
                    const u64* Ar = (const u64*)(As + (v+j)*34);
                    #pragma unroll
                    for (int k = 0; k < 16; k++) a1[k] = ffma2(Ar[k], da, a1[k]);
                }
            }
        }

        __syncthreads();   // all reads of As done before overwrite
        float* hout = step ? h2 : h1;
        {
            float si = sinv[w1];
            #pragma unroll
            for (int k = 0; k < 16; k++) {
                float2 r = unp2(a1[k]);
                float x0 = xr[(2*k)*400 + w1], x1v = xr[(2*k+1)*400 + w1];
                float o0 = AL*x0 + OMA*r.x, o1 = AL*x1v + OMA*r.y;
                hout[(2*k)*400 + w1] = o0;
                hout[(2*k+1)*400 + w1] = o1;
                if (step == 0) { As[w1*34 + 2*k] = o0*si; As[w1*34 + 2*k + 1] = o1*si; }
            }
        }
        if (ok2) {
            float si = sinv[w2];
            #pragma unroll
            for (int k = 0; k < 16; k++) {
                float2 r = unp2(a2[k]);
                float x0 = xr[(2*k)*400 + w2], x1v = xr[(2*k+1)*400 + w2];
                float o0 = AL*x0 + OMA*r.x, o1 = AL*x1v + OMA*r.y;
                hout[(2*k)*400 + w2] = o0;
                hout[(2*k+1)*400 + w2] = o1;
                if (step == 0) { As[w2*34 + 2*k] = o0*si; As[w2*34 + 2*k + 1] = o1*si; }
            }
        }
        __syncthreads();   // As ready for next step
    }
}

// ================= K5: combined MLP (160-wide) + output =================
__global__ void __launch_bounds__(256) k5(const float* __restrict__ wm1, const float* __restrict__ bm1,
                                          const float* __restrict__ wm2, const float* __restrict__ bm2,
                                          float* __restrict__ out)
{
    __shared__ u64 wc[160][16];
    __shared__ u64 bc[16];
    __shared__ const float* catp[160];
    int t = threadIdx.x, b = blockIdx.x;

    for (int i = t; i < 2560; i += 256) {
        int j = i >> 4, k = i & 15;
        float v0, v1;
        if (j < 32) {
            v0 = wm1[(2*k)*96 + j]   + wm2[(2*k)*96 + j];
            v1 = wm1[(2*k+1)*96 + j] + wm2[(2*k+1)*96 + j];
        } else if (j < 96) {
            v0 = wm1[(2*k)*96 + j];
            v1 = wm1[(2*k+1)*96 + j];
        } else {
            v0 = wm2[(2*k)*96 + j - 64];
            v1 = wm2[(2*k+1)*96 + j - 64];
        }
        wc[j][k] = pack2(v0, v1);
    }
    if (t < 16) bc[t] = pack2(bm1[2*t] + bm2[2*t], bm1[2*t+1] + bm2[2*t+1]);
    if (t < 160) {
        const float* p;
        if (t < 32)       p = g_xr  + b*CV + t*400;
        else if (t < 64)  p = g_h10 + b*CV + (t-32)*400;
        else if (t < 96)  p = g_h20 + b*CV + (t-64)*400;
        else if (t < 128) p = g_h11 + b*CV + (t-96)*400;
        else              p = g_h21 + b*CV + (t-128)*400;
        catp[t] = p;
    }
    __syncthreads();

    int n = b / 12, l = b - n*12;
    for (int w = t; w < 400; w += 256) {
        u64 acc[16];
        #pragma unroll
        for (int k = 0; k < 16; k++) acc[k] = bc[k];
        #pragma unroll 4
        for (int j = 0; j < 160; j++) {
            u64 d = dup2(catp[j][w]);
            #pragma unroll
            for (int k = 0; k < 16; k++) acc[k] = ffma2(wc[j][k], d, acc[k]);
        }
        #pragma unroll
        for (int k = 0; k < 16; k++) {
            float2 r = unp2(acc[k]);
            out[((n*32 + 2*k)*400 + w)*12 + l]   = r.x;
            out[((n*32 + 2*k+1)*400 + w)*12 + l] = r.y;
        }
    }
}

// ================= launch =================
extern "C" void kernel_launch(void* const* d_in, const int* in_sizes, int n_in,
                              void* d_out, int out_size)
{
    const float* x   = (const float*)d_in[0];
    const float* w1  = (const float*)d_in[1];
    const float* b1  = (const float*)d_in[2];
    const float* w2  = (const float*)d_in[3];
    const float* b2  = (const float*)d_in[4];
    const float* wm1 = (const float*)d_in[5];
    const float* bm1 = (const float*)d_in[6];
    const float* wm2 = (const float*)d_in[7];
    const float* bm2 = (const float*)d_in[8];
    float* out = (float*)d_out;

    cudaFuncSetAttribute(k4, cudaFuncAttributeMaxDynamicSharedMemorySize, (400*34 + 400) * 4);

    k1<<<384, 256>>>(x, w1, b1, w2, b2);
    k2<32><<<dim3(384, 6), 416>>>(0, 0);     // v-tiles 0..5 (64 rows each)
    k2<8><<<dim3(384, 1), 416>>>(384, 6);    // tail tile (16 rows)
    k3<<<600, 256>>>();
    k4<<<dim3(384, 2), 256, (400*34 + 400) * 4>>>();
    k5<<<384, 256>>>(wm1, bm1, wm2, bm2, out);
}